// round 2
// baseline (speedup 1.0000x reference)
#include <cuda_runtime.h>

// Magnus2: x_{n+1} = E_n x_n with 2x2 time-dependent E_n.
// Strategy: E_n is batch-independent -> parallel prefix product over 2x2
// matrices (fp64 combine), then embarrassingly-parallel y[n] = P[n] @ x0.

#define MAX_T 8192

// Scratch (allocation-free rule: __device__ globals).
__device__ float4 g_E[MAX_T];   // slot 0 = I, slot k = E_{k-1} (k>=1)
__device__ float4 g_P[MAX_T];   // P[n] = E_{n-1} ... E_0  (P[0] = I)

// ---------------------------------------------------------------------------
// Kernel 1: compute propagators E_i for segments i = 0..T-2 (fp32, matches
// reference precision). Closed-form commutator: [A0,A1] = [[0,dg],[w*dg,0]].
// ---------------------------------------------------------------------------
__global__ void __launch_bounds__(256)
compute_E_kernel(const float* __restrict__ t,
                 const float* __restrict__ p_w,
                 const float* __restrict__ p_g0,
                 const float* __restrict__ p_ga,
                 const float* __restrict__ p_wd,
                 const int*   __restrict__ p_uc,
                 int T)
{
    int i = blockIdx.x * blockDim.x + threadIdx.x;
    if (i >= T - 1) return;

    const float w  = *p_w;
    const float g0 = *p_g0;
    const float ga = *p_ga;
    const float wd = *p_wd;
    const int   uc = *p_uc;

    const float t0 = t[i];
    const float t1 = t[i + 1];
    const float dt = t1 - t0;
    const float tm = t0 + dt * 0.5f;

    const float gm = g0 * (1.0f + ga * sinf(wd * tm));

    // Omega = A_mid * dt (+ dt^2/12 * [A0, A1])
    float O00 = 0.0f;
    float O01 = dt;
    float O10 = -w * dt;
    float O11 = -gm * dt;
    if (uc) {
        const float gA = g0 * (1.0f + ga * sinf(wd * t0));
        const float gB = g0 * (1.0f + ga * sinf(wd * t1));
        const float dg = gA - gB;
        const float c  = dt * dt * (1.0f / 12.0f);
        O01 += c * dg;
        O10 += c * w * dg;
    }

    // expm of 2x2 (same branch structure as reference)
    const float m     = 0.5f * (O00 + O11);
    const float det   = O00 * O11 - O01 * O10;
    const float delta = m * m - det;
    const float s     = sqrtf(fabsf(delta));
    const bool  pos   = (delta >= 0.0f);
    const bool  sm    = (s < 1e-6f);
    const float ssafe = sm ? 1.0f : s;
    const float cosl  = pos ? coshf(s) : cosf(s);
    const float sinch = sm ? 1.0f : ((pos ? sinhf(ssafe) : sinf(ssafe)) / ssafe);
    const float em    = expf(m);

    float4 E;
    E.x = em * (cosl + sinch * (O00 - m));
    E.y = em * (sinch * O01);
    E.z = em * (sinch * O10);
    E.w = em * (cosl + sinch * (O11 - m));

    g_E[i + 1] = E;
    if (i == 0) g_E[0] = make_float4(1.0f, 0.0f, 0.0f, 1.0f);
}

// ---------------------------------------------------------------------------
// Kernel 2: inclusive prefix product of the 2x2 matrices in fp64.
// One block, 1024 threads, 8 slots/thread; Kogge-Stone over aggregates.
// Combine(newer, older) = newer @ older.
// ---------------------------------------------------------------------------
struct M2 { double a, b, c, d; };

__device__ __forceinline__ M2 mmul(const M2& X, const M2& Y) {  // X @ Y
    M2 r;
    r.a = X.a * Y.a + X.b * Y.c;
    r.b = X.a * Y.b + X.b * Y.d;
    r.c = X.c * Y.a + X.d * Y.c;
    r.d = X.c * Y.b + X.d * Y.d;
    return r;
}

__global__ void __launch_bounds__(1024)
scan_kernel(int T)
{
    __shared__ M2 smem[1024];
    const int tid  = threadIdx.x;
    const int base = tid * 8;

    // local inclusive products over 8 slots (identity for padding slots)
    M2 L[8];
    {
        M2 S;
        if (base < T) {
            float4 e = g_E[base];
            S = { (double)e.x, (double)e.y, (double)e.z, (double)e.w };
        } else {
            S = { 1.0, 0.0, 0.0, 1.0 };
        }
        L[0] = S;
        #pragma unroll
        for (int j = 1; j < 8; j++) {
            int k = base + j;
            if (k < T) {
                float4 e = g_E[k];
                S = { (double)e.x, (double)e.y, (double)e.z, (double)e.w };
                L[j] = mmul(S, L[j - 1]);
            } else {
                L[j] = L[j - 1];
            }
        }
    }

    M2 agg = L[7];
    smem[tid] = agg;
    __syncthreads();

    #pragma unroll
    for (int off = 1; off < 1024; off <<= 1) {
        M2 prev;
        const bool has = (tid >= off);
        if (has) prev = smem[tid - off];
        __syncthreads();
        if (has) agg = mmul(agg, prev);
        smem[tid] = agg;
        __syncthreads();
    }

    M2 excl;
    const bool hase = (tid > 0);
    if (hase) excl = smem[tid - 1];

    #pragma unroll
    for (int j = 0; j < 8; j++) {
        const int k = base + j;
        if (k >= T) break;
        M2 P = hase ? mmul(L[j], excl) : L[j];
        g_P[k] = make_float4((float)P.a, (float)P.b, (float)P.c, (float)P.d);
    }
}

// ---------------------------------------------------------------------------
// Kernel 3: y[n] = P[n] @ x0 for all n, batch-vectorized with float4.
// out layout (T, 2, B); x0 layout (2, B). HBM-store bound.
// ---------------------------------------------------------------------------
__global__ void __launch_bounds__(256)
out_kernel(const float* __restrict__ x0,
           float* __restrict__ out,
           int B)
{
    const int n  = blockIdx.y;
    const int b4 = blockIdx.x * blockDim.x + threadIdx.x;  // float4 index in B
    const int B4 = B >> 2;
    if (b4 >= B4) return;

    const float4 P = g_P[n];

    const float4* __restrict__ x0r0 = (const float4*)x0;
    const float4* __restrict__ x0r1 = (const float4*)(x0 + B);
    const float4 a0 = x0r0[b4];
    const float4 a1 = x0r1[b4];

    float4 y0, y1;
    y0.x = P.x * a0.x + P.y * a1.x;
    y0.y = P.x * a0.y + P.y * a1.y;
    y0.z = P.x * a0.z + P.y * a1.z;
    y0.w = P.x * a0.w + P.y * a1.w;
    y1.x = P.z * a0.x + P.w * a1.x;
    y1.y = P.z * a0.y + P.w * a1.y;
    y1.z = P.z * a0.z + P.w * a1.z;
    y1.w = P.z * a0.w + P.w * a1.w;

    float4* __restrict__ o0 = (float4*)(out + (size_t)n * 2 * B);
    float4* __restrict__ o1 = o0 + B4;
    o0[b4] = y0;
    o1[b4] = y1;
}

// ---------------------------------------------------------------------------
extern "C" void kernel_launch(void* const* d_in, const int* in_sizes, int n_in,
                              void* d_out, int out_size)
{
    const float* t   = (const float*)d_in[0];
    const float* x0  = (const float*)d_in[1];
    const float* w   = (const float*)d_in[2];
    const float* g0  = (const float*)d_in[3];
    const float* ga  = (const float*)d_in[4];
    const float* wd  = (const float*)d_in[5];
    const int*   uc  = (const int*)d_in[6];
    float* out = (float*)d_out;

    const int T = in_sizes[0];          // 8192
    const int B = in_sizes[1] / 2;      // 4096

    // Kernel 1: propagators
    {
        int n = T - 1;
        int blocks = (n + 255) / 256;
        compute_E_kernel<<<blocks, 256>>>(t, w, g0, ga, wd, uc, T);
    }
    // Kernel 2: prefix product (single block)
    scan_kernel<<<1, 1024>>>(T);

    // Kernel 3: outputs
    {
        int B4 = B >> 2;
        dim3 block(256);
        dim3 grid((B4 + 255) / 256, T);
        out_kernel<<<grid, block>>>(x0, out, B);
    }
}

// round 3
// speedup vs baseline: 2.4056x; 2.4056x over previous
#include <cuda_runtime.h>

// Magnus2: x_{n+1} = E_n x_n, 2x2 time-dependent, batch-independent E.
// Pipeline:
//   K1: per-block (128 slots) compute E + local fp32 prefix product -> g_L, g_agg
//   K2: 1 block: fp64 scan of 64 block aggregates + fp32 fixup -> g_P
//   K3: y[n] = P[n] @ x0, store-bandwidth bound (streaming stores)

#define MAX_T   8192
#define SLOTS_PER_BLK 128
#define MAX_NB  (MAX_T / SLOTS_PER_BLK)   // 64
#define NCHUNK  32                         // n-rows per out-block

__device__ float4 g_L[MAX_T];     // block-local inclusive products
__device__ float4 g_agg[MAX_NB];  // per-block aggregates
__device__ float4 g_P[MAX_T];     // global prefix products (final)

// ---------------------------------------------------------------------------
// fp32 2x2 multiply: R = X @ Y  (packed row-major: x=00 y=01 z=10 w=11)
// ---------------------------------------------------------------------------
__device__ __forceinline__ float4 mmul32(float4 X, float4 Y) {
    float4 r;
    r.x = X.x * Y.x + X.y * Y.z;
    r.y = X.x * Y.y + X.y * Y.w;
    r.z = X.z * Y.x + X.w * Y.z;
    r.w = X.z * Y.y + X.w * Y.w;
    return r;
}

struct M2d { double a, b, c, d; };
__device__ __forceinline__ M2d mmul64(const M2d& X, const M2d& Y) {
    M2d r;
    r.a = X.a * Y.a + X.b * Y.c;
    r.b = X.a * Y.b + X.b * Y.d;
    r.c = X.c * Y.a + X.d * Y.c;
    r.d = X.c * Y.b + X.d * Y.d;
    return r;
}

// ---------------------------------------------------------------------------
// K1: compute E for this block's 128 slots, then local Kogge-Stone scan.
// slot 0 = I; slot k (k>=1) = propagator of segment k-1.
// ---------------------------------------------------------------------------
__global__ void __launch_bounds__(SLOTS_PER_BLK)
k1_E_localscan(const float* __restrict__ t,
               const float* __restrict__ p_w,
               const float* __restrict__ p_g0,
               const float* __restrict__ p_ga,
               const float* __restrict__ p_wd,
               const int*   __restrict__ p_uc,
               int T)
{
    __shared__ float4 sm[SLOTS_PER_BLK];
    const int tid = threadIdx.x;
    const int s   = blockIdx.x * SLOTS_PER_BLK + tid;

    float4 E = make_float4(1.0f, 0.0f, 0.0f, 1.0f);
    if (s >= 1 && s < T) {
        const float w  = *p_w;
        const float g0 = *p_g0;
        const float ga = *p_ga;
        const float wd = *p_wd;
        const int   uc = *p_uc;

        const int i = s - 1;
        const float t0 = t[i];
        const float t1 = t[i + 1];
        const float dt = t1 - t0;
        const float tm = t0 + dt * 0.5f;
        const float gm = g0 * (1.0f + ga * sinf(wd * tm));

        float O00 = 0.0f;
        float O01 = dt;
        float O10 = -w * dt;
        float O11 = -gm * dt;
        if (uc) {
            const float gA = g0 * (1.0f + ga * sinf(wd * t0));
            const float gB = g0 * (1.0f + ga * sinf(wd * t1));
            const float dg = gA - gB;
            const float c  = dt * dt * (1.0f / 12.0f);
            O01 += c * dg;
            O10 += c * w * dg;
        }

        const float m     = 0.5f * (O00 + O11);
        const float det   = O00 * O11 - O01 * O10;
        const float delta = m * m - det;
        const float sq    = sqrtf(fabsf(delta));
        const bool  pos   = (delta >= 0.0f);
        const bool  smll  = (sq < 1e-6f);
        const float ssafe = smll ? 1.0f : sq;
        const float cosl  = pos ? coshf(sq) : cosf(sq);
        const float sinch = smll ? 1.0f : ((pos ? sinhf(ssafe) : sinf(ssafe)) / ssafe);
        const float em    = expf(m);

        E.x = em * (cosl + sinch * (O00 - m));
        E.y = em * (sinch * O01);
        E.z = em * (sinch * O10);
        E.w = em * (cosl + sinch * (O11 - m));
    }

    // Kogge-Stone inclusive scan (combine: newer @ older)
    float4 agg = E;
    sm[tid] = agg;
    __syncthreads();
    #pragma unroll
    for (int off = 1; off < SLOTS_PER_BLK; off <<= 1) {
        float4 prev;
        const bool has = (tid >= off);
        if (has) prev = sm[tid - off];
        __syncthreads();
        if (has) agg = mmul32(agg, prev);
        sm[tid] = agg;
        __syncthreads();
    }

    if (s < T) g_L[s] = agg;
    if (tid == SLOTS_PER_BLK - 1) g_agg[blockIdx.x] = agg;
}

// ---------------------------------------------------------------------------
// K2: scan the NB block aggregates in fp64 (long-range chain), then fp32
// fixup of all T prefix products.
// ---------------------------------------------------------------------------
__global__ void __launch_bounds__(1024)
k2_aggscan_fixup(int T, int NB)
{
    __shared__ M2d  sA[MAX_NB];
    __shared__ float4 sPref[MAX_NB];   // exclusive prefix per block (fp32)
    const int tid = threadIdx.x;

    if (tid < MAX_NB) {
        M2d v = {1.0, 0.0, 0.0, 1.0};
        if (tid < NB) {
            float4 a = g_agg[tid];
            v = { (double)a.x, (double)a.y, (double)a.z, (double)a.w };
        }
        sA[tid] = v;
    }
    __syncthreads();

    // Kogge-Stone fp64 over MAX_NB entries (only first 64 threads active)
    if (tid < MAX_NB) {
        M2d agg = sA[tid];
        #pragma unroll
        for (int off = 1; off < MAX_NB; off <<= 1) {
            M2d prev;
            const bool has = (tid >= off);
            if (has) prev = sA[tid - off];
            __syncthreads();
            if (has) agg = mmul64(agg, prev);
            sA[tid] = agg;
            __syncthreads();
        }
        // exclusive prefix (fp32 for fixup)
        M2d ex = {1.0, 0.0, 0.0, 1.0};
        if (tid > 0) ex = sA[tid - 1];
        sPref[tid] = make_float4((float)ex.a, (float)ex.b, (float)ex.c, (float)ex.d);
    } else {
        // non-participants must still hit the barriers
        #pragma unroll
        for (int off = 1; off < MAX_NB; off <<= 1) { __syncthreads(); __syncthreads(); }
    }
    __syncthreads();

    // fixup: P[n] = L[n] @ pref[n / SLOTS_PER_BLK]
    for (int n = tid; n < T; n += 1024) {
        float4 L = g_L[n];
        float4 pr = sPref[n >> 7];   // SLOTS_PER_BLK == 128
        g_P[n] = mmul32(L, pr);
    }
}

// ---------------------------------------------------------------------------
// K3: y[n] = P[n] @ x0, each thread holds its x0 column and writes NCHUNK rows.
// out layout (T, 2, B); streaming stores.
// ---------------------------------------------------------------------------
__global__ void __launch_bounds__(256)
k3_out(const float* __restrict__ x0,
       float* __restrict__ out,
       int B, int T)
{
    __shared__ float4 sP[NCHUNK];
    const int tid = threadIdx.x;
    const int B4  = B >> 2;
    const int b4  = blockIdx.x * 256 + tid;
    const int n0  = blockIdx.y * NCHUNK;

    if (tid < NCHUNK) {
        int nn = n0 + tid;
        sP[tid] = g_P[nn < T ? nn : (T - 1)];
    }
    __syncthreads();

    if (b4 >= B4) return;

    const float4 a0 = ((const float4*)x0)[b4];
    const float4 a1 = ((const float4*)(x0 + B))[b4];

    #pragma unroll 4
    for (int j = 0; j < NCHUNK; j++) {
        const int n = n0 + j;
        if (n >= T) break;
        const float4 P = sP[j];

        float4 y0, y1;
        y0.x = P.x * a0.x + P.y * a1.x;
        y0.y = P.x * a0.y + P.y * a1.y;
        y0.z = P.x * a0.z + P.y * a1.z;
        y0.w = P.x * a0.w + P.y * a1.w;
        y1.x = P.z * a0.x + P.w * a1.x;
        y1.y = P.z * a0.y + P.w * a1.y;
        y1.z = P.z * a0.z + P.w * a1.z;
        y1.w = P.z * a0.w + P.w * a1.w;

        float4* o0 = (float4*)(out + (size_t)n * 2 * B);
        __stcs(o0 + b4, y0);
        __stcs(o0 + B4 + b4, y1);
    }
}

// ---------------------------------------------------------------------------
extern "C" void kernel_launch(void* const* d_in, const int* in_sizes, int n_in,
                              void* d_out, int out_size)
{
    const float* t  = (const float*)d_in[0];
    const float* x0 = (const float*)d_in[1];
    const float* w  = (const float*)d_in[2];
    const float* g0 = (const float*)d_in[3];
    const float* ga = (const float*)d_in[4];
    const float* wd = (const float*)d_in[5];
    const int*   uc = (const int*)d_in[6];
    float* out = (float*)d_out;

    const int T = in_sizes[0];       // 8192
    const int B = in_sizes[1] / 2;   // 4096
    const int NB = (T + SLOTS_PER_BLK - 1) / SLOTS_PER_BLK;   // 64

    k1_E_localscan<<<NB, SLOTS_PER_BLK>>>(t, w, g0, ga, wd, uc, T);
    k2_aggscan_fixup<<<1, 1024>>>(T, NB);

    {
        const int B4 = B >> 2;
        dim3 grid((B4 + 255) / 256, (T + NCHUNK - 1) / NCHUNK);
        k3_out<<<grid, 256>>>(x0, out, B, T);
    }
}